// round 4
// baseline (speedup 1.0000x reference)
#include <cuda_runtime.h>
#include <cuda_bf16.h>

// Weighted keypoint MSE loss, single fused kernel:
//   oob = target outside [0,1024]^2; weight = oob ? 0.01 : 1.0
//   loss = sum_bk( weight * ||output-target||^2 ) / 4096
//
// R4: software-pipelined loads (register double-buffer, 4 LDG.128 always in
// flight per thread), uniform iteration count with predicated tail,
// grid = 148*8 exact wave, 32-bit indexing, last-block finalize.

#define HEIGHT_F 1024.0f
#define WIDTH_F  1024.0f
#define OOB_W    0.01f
#define B_DIM    4096.0

#define NBLOCKS  1184   // 148 SMs * 8 CTAs
#define NTHREADS 256

__device__ double g_partials[NBLOCKS];
__device__ unsigned int g_count;   // zero-init; atomicInc self-wraps -> replay-safe

__device__ __forceinline__ float pair_loss(float4 o, float4 t) {
    float dx0 = o.x - t.x;
    float dy0 = o.y - t.y;
    float sq0 = fmaf(dx0, dx0, dy0 * dy0);
    bool oob0 = (t.x < 0.0f) | (t.x > WIDTH_F) | (t.y < 0.0f) | (t.y > HEIGHT_F);
    float w0 = oob0 ? OOB_W : 1.0f;

    float dx1 = o.z - t.z;
    float dy1 = o.w - t.w;
    float sq1 = fmaf(dx1, dx1, dy1 * dy1);
    bool oob1 = (t.z < 0.0f) | (t.z > WIDTH_F) | (t.w < 0.0f) | (t.w > HEIGHT_F);
    float w1 = oob1 ? OOB_W : 1.0f;

    return fmaf(w0, sq0, w1 * sq1);
}

__device__ __forceinline__ double block_reduce(double v, double* warp_sums) {
    #pragma unroll
    for (int off = 16; off > 0; off >>= 1)
        v += __shfl_down_sync(0xFFFFFFFFu, v, off);
    int lane = threadIdx.x & 31;
    int wid  = threadIdx.x >> 5;
    if (lane == 0) warp_sums[wid] = v;
    __syncthreads();
    if (wid == 0) {
        v = (lane < (NTHREADS >> 5)) ? warp_sums[lane] : 0.0;
        #pragma unroll
        for (int off = 4; off > 0; off >>= 1)
            v += __shfl_down_sync(0xFFFFFFFFu, v, off);
    }
    return v;  // valid in thread 0
}

__global__ __launch_bounds__(NTHREADS, 6) void loss_kernel(
    const float4* __restrict__ outp,
    const float4* __restrict__ tgt,
    int n4,
    float* __restrict__ out)
{
    const int stride = NBLOCKS * NTHREADS;   // 303104
    const int step   = 2 * stride;
    const int base   = blockIdx.x * NTHREADS + threadIdx.x;

    const int nIter = (n4 + step - 1) / step;   // uniform across all threads (14)

    // ---- prologue: issue iteration 0's loads ----
    int  i0 = base;
    int  i1 = base + stride;
    bool v0 = i0 < n4;
    bool v1 = i1 < n4;
    float4 o0 = __ldcs(outp + (v0 ? i0 : 0));
    float4 t0 = __ldcs(tgt  + (v0 ? i0 : 0));
    float4 o1 = __ldcs(outp + (v1 ? i1 : 0));
    float4 t1 = __ldcs(tgt  + (v1 ? i1 : 0));

    double acc = 0.0;

    // ---- steady state: prefetch k+1 while consuming k ----
    for (int k = 1; k < nIter; k++) {
        int  j0 = base + k * step;
        int  j1 = j0 + stride;
        bool w0 = j0 < n4;
        bool w1 = j1 < n4;
        float4 no0 = __ldcs(outp + (w0 ? j0 : 0));
        float4 nt0 = __ldcs(tgt  + (w0 ? j0 : 0));
        float4 no1 = __ldcs(outp + (w1 ? j1 : 0));
        float4 nt1 = __ldcs(tgt  + (w1 ? j1 : 0));

        float s = 0.0f;
        if (v0) s += pair_loss(o0, t0);
        if (v1) s += pair_loss(o1, t1);
        acc += (double)s;

        o0 = no0; t0 = nt0; o1 = no1; t1 = nt1;
        v0 = w0;  v1 = w1;
    }
    // ---- epilogue: consume final iteration ----
    {
        float s = 0.0f;
        if (v0) s += pair_loss(o0, t0);
        if (v1) s += pair_loss(o1, t1);
        acc += (double)s;
    }

    __shared__ double warp_sums[NTHREADS / 32];
    __shared__ bool is_last;

    double bsum = block_reduce(acc, warp_sums);

    if (threadIdx.x == 0) {
        g_partials[blockIdx.x] = bsum;
        __threadfence();
        unsigned int old = atomicInc(&g_count, NBLOCKS - 1);  // wraps to 0
        is_last = (old == NBLOCKS - 1);
    }
    __syncthreads();

    if (is_last) {
        __threadfence();
        double v = 0.0;
        for (int j = threadIdx.x; j < NBLOCKS; j += NTHREADS)
            v += g_partials[j];
        __syncthreads();
        double total = block_reduce(v, warp_sums);
        if (threadIdx.x == 0)
            out[0] = (float)(total / B_DIM);
    }
}

extern "C" void kernel_launch(void* const* d_in, const int* in_sizes, int n_in,
                              void* d_out, int out_size) {
    const float4* outp = (const float4*)d_in[0];
    const float4* tgt  = (const float4*)d_in[1];
    int n4 = in_sizes[0] / 4;   // float4 count (2 keypoints each)

    loss_kernel<<<NBLOCKS, NTHREADS>>>(outp, tgt, n4, (float*)d_out);
}

// round 5
// speedup vs baseline: 1.1706x; 1.1706x over previous
#include <cuda_runtime.h>
#include <cuda_bf16.h>
#include <cstdint>

// Weighted keypoint MSE loss:
//   oob = target outside [0,1024]^2; weight = oob ? 0.01 : 1.0
//   loss = sum_bk( weight * ||output-target||^2 ) / 4096
//
// R5: TMA (cp.async.bulk 1D) producer pipeline -> 4-stage smem ring,
// 256 consumer threads/CTA, grid = 148*4. Loads are decoupled from warp
// scoreboards so DRAM stays saturated. Last-block finalize as before.

#define HEIGHT_F 1024.0f
#define WIDTH_F  1024.0f
#define OOB_W    0.01f
#define B_DIM    4096.0

#define NBLOCKS   592            // 148 SMs * 4 CTAs
#define NTHREADS  256
#define NSTAGES   4
#define CHUNK_F4  256            // float4 per chunk per array (4KB)
#define CHUNK_BYTES (CHUNK_F4 * 16)

__device__ double g_partials[NBLOCKS];
__device__ unsigned int g_count;   // zero-init; atomicInc self-wraps -> replay-safe

__device__ __forceinline__ uint32_t smem_u32(const void* p) {
    return (uint32_t)__cvta_generic_to_shared(p);
}

__device__ __forceinline__ void mbar_init(uint32_t mbar, uint32_t count) {
    asm volatile("mbarrier.init.shared.b64 [%0], %1;" :: "r"(mbar), "r"(count) : "memory");
}

__device__ __forceinline__ void mbar_expect_tx(uint32_t mbar, uint32_t bytes) {
    asm volatile("mbarrier.arrive.expect_tx.shared.b64 _, [%0], %1;"
                 :: "r"(mbar), "r"(bytes) : "memory");
}

__device__ __forceinline__ void mbar_wait(uint32_t mbar, uint32_t parity) {
    uint32_t done;
    asm volatile(
        "{\n\t.reg .pred p;\n\t"
        "mbarrier.try_wait.parity.acquire.cta.shared::cta.b64 p, [%1], %2;\n\t"
        "selp.b32 %0, 1, 0, p;\n\t}"
        : "=r"(done) : "r"(mbar), "r"(parity) : "memory");
    if (!done) {
        asm volatile(
            "{\n\t.reg .pred P1;\n\t"
            "WAIT_LOOP_%=:\n\t"
            "mbarrier.try_wait.parity.acquire.cta.shared::cta.b64 P1, [%0], %1, 0x989680;\n\t"
            "@P1 bra.uni WAIT_DONE_%=;\n\t"
            "bra.uni WAIT_LOOP_%=;\n\t"
            "WAIT_DONE_%=:\n\t}"
            :: "r"(mbar), "r"(parity) : "memory");
    }
}

__device__ __forceinline__ void bulk_g2s(uint32_t dst_smem, const void* src_gmem,
                                         uint32_t bytes, uint32_t mbar) {
    asm volatile(
        "cp.async.bulk.shared::cta.global.mbarrier::complete_tx::bytes [%0], [%1], %2, [%3];"
        :: "r"(dst_smem), "l"(src_gmem), "r"(bytes), "r"(mbar) : "memory");
}

__device__ __forceinline__ float pair_loss(float4 o, float4 t) {
    float dx0 = o.x - t.x;
    float dy0 = o.y - t.y;
    float sq0 = fmaf(dx0, dx0, dy0 * dy0);
    bool oob0 = (t.x < 0.0f) | (t.x > WIDTH_F) | (t.y < 0.0f) | (t.y > HEIGHT_F);
    float w0 = oob0 ? OOB_W : 1.0f;

    float dx1 = o.z - t.z;
    float dy1 = o.w - t.w;
    float sq1 = fmaf(dx1, dx1, dy1 * dy1);
    bool oob1 = (t.z < 0.0f) | (t.z > WIDTH_F) | (t.w < 0.0f) | (t.w > HEIGHT_F);
    float w1 = oob1 ? OOB_W : 1.0f;

    return fmaf(w0, sq0, w1 * sq1);
}

__device__ __forceinline__ double block_reduce(double v, double* warp_sums) {
    #pragma unroll
    for (int off = 16; off > 0; off >>= 1)
        v += __shfl_down_sync(0xFFFFFFFFu, v, off);
    int lane = threadIdx.x & 31;
    int wid  = threadIdx.x >> 5;
    if (lane == 0) warp_sums[wid] = v;
    __syncthreads();
    if (wid == 0) {
        v = (lane < (NTHREADS >> 5)) ? warp_sums[lane] : 0.0;
        #pragma unroll
        for (int off = 4; off > 0; off >>= 1)
            v += __shfl_down_sync(0xFFFFFFFFu, v, off);
    }
    return v;  // valid in thread 0
}

__global__ __launch_bounds__(NTHREADS) void loss_kernel(
    const float4* __restrict__ outp,
    const float4* __restrict__ tgt,
    int n4,
    float* __restrict__ out)
{
    __shared__ __align__(16) float4 s_o[NSTAGES][CHUNK_F4];
    __shared__ __align__(16) float4 s_t[NSTAGES][CHUNK_F4];
    __shared__ __align__(8)  unsigned long long s_mbar[NSTAGES];
    __shared__ double warp_sums[NTHREADS / 32];
    __shared__ bool is_last;

    const int tid = threadIdx.x;
    const int chunks_total = n4 / CHUNK_F4;   // full chunks (tail handled below)

    if (tid == 0) {
        #pragma unroll
        for (int s = 0; s < NSTAGES; s++)
            mbar_init(smem_u32(&s_mbar[s]), 1);
    }
    __syncthreads();

    // ---- prologue: fill the ring ----
    if (tid == 0) {
        #pragma unroll
        for (int p = 0; p < NSTAGES; p++) {
            int c = blockIdx.x + p * NBLOCKS;
            if (c < chunks_total) {
                uint32_t mb = smem_u32(&s_mbar[p]);
                mbar_expect_tx(mb, 2 * CHUNK_BYTES);
                bulk_g2s(smem_u32(&s_o[p][0]), outp + (size_t)c * CHUNK_F4, CHUNK_BYTES, mb);
                bulk_g2s(smem_u32(&s_t[p][0]), tgt  + (size_t)c * CHUNK_F4, CHUNK_BYTES, mb);
            }
        }
    }

    double acc = 0.0;

    // ---- main pipeline ----
    int k = 0;
    for (int c = blockIdx.x; c < chunks_total; c += NBLOCKS, k++) {
        int s = k & (NSTAGES - 1);
        uint32_t parity = (k >> 2) & 1;
        uint32_t mb = smem_u32(&s_mbar[s]);

        mbar_wait(mb, parity);

        float4 o = s_o[s][tid];
        float4 t = s_t[s][tid];
        acc += (double)pair_loss(o, t);

        __syncthreads();   // everyone done reading stage s

        if (tid == 0) {
            int cn = c + NSTAGES * NBLOCKS;
            if (cn < chunks_total) {
                mbar_expect_tx(mb, 2 * CHUNK_BYTES);
                bulk_g2s(smem_u32(&s_o[s][0]), outp + (size_t)cn * CHUNK_F4, CHUNK_BYTES, mb);
                bulk_g2s(smem_u32(&s_t[s][0]), tgt  + (size_t)cn * CHUNK_F4, CHUNK_BYTES, mb);
            }
        }
    }

    // ---- tail (n4 not a multiple of CHUNK_F4): block 0 via plain LDG ----
    if (blockIdx.x == 0) {
        for (int i = chunks_total * CHUNK_F4 + tid; i < n4; i += NTHREADS) {
            float4 o = __ldcs(outp + i);
            float4 t = __ldcs(tgt + i);
            acc += (double)pair_loss(o, t);
        }
    }

    // ---- reduce + last-block finalize ----
    double bsum = block_reduce(acc, warp_sums);

    if (tid == 0) {
        g_partials[blockIdx.x] = bsum;
        __threadfence();
        unsigned int old = atomicInc(&g_count, NBLOCKS - 1);  // wraps to 0
        is_last = (old == NBLOCKS - 1);
    }
    __syncthreads();

    if (is_last) {
        __threadfence();
        double v = 0.0;
        for (int j = tid; j < NBLOCKS; j += NTHREADS)
            v += g_partials[j];
        __syncthreads();
        double total = block_reduce(v, warp_sums);
        if (tid == 0)
            out[0] = (float)(total / B_DIM);
    }
}

extern "C" void kernel_launch(void* const* d_in, const int* in_sizes, int n_in,
                              void* d_out, int out_size) {
    const float4* outp = (const float4*)d_in[0];
    const float4* tgt  = (const float4*)d_in[1];
    int n4 = in_sizes[0] / 4;   // float4 count (2 keypoints each)

    loss_kernel<<<NBLOCKS, NTHREADS>>>(outp, tgt, n4, (float*)d_out);
}